// round 15
// baseline (speedup 1.0000x reference)
#include <cuda_runtime.h>
#include <cuda_bf16.h>
#include <cstdint>
#include <cstddef>

#define HIDDEN 1024
#define NHEAD  16
#define HD     64
#define BATCH  2
#define SEQ    2048
#define M_TOTAL 4096
#define BH      32
#define CTX_SIZE ((size_t)BATCH * SEQ * HIDDEN)   // 4,194,304
#define XN (M_TOTAL * HIDDEN)
#define WN (HIDDEN * HIDDEN)                      // 1<<20

typedef unsigned long long u64;

// fp32 Q/K/V scratch (consumed by proven SIMT scores/ctx kernels)
__device__ __align__(256) float g_q[(size_t)BH * SEQ * HD];
__device__ __align__(256) float g_k[(size_t)BH * SEQ * HD];
__device__ __align__(256) float g_v[(size_t)BH * SEQ * HD];
__device__ __align__(256) float g_rsum[BH * SEQ];
// split-bf16 inputs for HMMA qkv
__device__ __align__(256) __nv_bfloat16 g_xhi[XN], g_xlo[XN];
__device__ __align__(256) __nv_bfloat16 g_whi[3 * WN], g_wlo[3 * WN];

// ---- packed fp32x2 (SIMT kernels) ------------------------------------------
__device__ __forceinline__ void fma2(u64& d, u64 a, u64 b) {
    asm("fma.rn.f32x2 %0, %1, %2, %0;" : "+l"(d) : "l"(a), "l"(b));
}
__device__ __forceinline__ u64 pack2(float a) {
    u64 r;
    asm("mov.b64 %0, {%1, %1};" : "=l"(r) : "f"(a));
    return r;
}
__device__ __forceinline__ void unpack2(u64 v, float& lo, float& hi) {
    asm("mov.b64 {%0, %1}, %2;" : "=f"(lo), "=f"(hi) : "l"(v));
}

// ---- cp.async --------------------------------------------------------------
__device__ __forceinline__ void cpa16(unsigned sm, const void* g) {
    asm volatile("cp.async.cg.shared.global [%0], [%1], 16;" :: "r"(sm), "l"(g));
}
#define CPA_COMMIT() asm volatile("cp.async.commit_group;")
#define CPA_WAIT1()  asm volatile("cp.async.wait_group 1;")
#define CPA_WAIT0()  asm volatile("cp.async.wait_group 0;")

// ---- HMMA (baseline PTX, valid on sm_103 — NOT an 'a' feature) -------------
__device__ __forceinline__ void mma_bf16(float& c0, float& c1, float& c2, float& c3,
                                         unsigned a0, unsigned a1, unsigned a2, unsigned a3,
                                         unsigned b0, unsigned b1) {
    asm volatile(
        "mma.sync.aligned.m16n8k16.row.col.f32.bf16.bf16.f32 "
        "{%0,%1,%2,%3}, {%4,%5,%6,%7}, {%8,%9}, {%0,%1,%2,%3};"
        : "+f"(c0), "+f"(c1), "+f"(c2), "+f"(c3)
        : "r"(a0), "r"(a1), "r"(a2), "r"(a3), "r"(b0), "r"(b1));
}

__device__ __forceinline__ void split_bf(float x, __nv_bfloat16& h, __nv_bfloat16& l) {
    h = __float2bfloat16_rn(x);
    l = __float2bfloat16_rn(x - __bfloat162float(h));
}

// FMA-only exp. Rel err ~1e-7.
__device__ __forceinline__ float fexp(float x) {
    float t = x * 1.4426950408889634f;
    float fi = rintf(t);
    float y = (t - fi) * 0.6931471805599453f;
    float p = 1.3888889e-3f;
    p = fmaf(p, y, 8.3333333e-3f);
    p = fmaf(p, y, 4.1666667e-2f);
    p = fmaf(p, y, 1.6666667e-1f);
    p = fmaf(p, y, 0.5f);
    p = fmaf(p, y, 1.0f);
    p = fmaf(p, y, 1.0f);
    return p * __int_as_float(((int)fi + 127) << 23);
}

// ---------------------------------------------------------------------------
__global__ void zero_rsum_kernel() {
    g_rsum[blockIdx.x * 256 + threadIdx.x] = 0.0f;
}

__global__ void split_kernel(const float* __restrict__ X,
                             const float* __restrict__ Wq,
                             const float* __restrict__ Wk,
                             const float* __restrict__ Wv) {
    int i = blockIdx.x * 256 + threadIdx.x;
    __nv_bfloat16 h, l;
    if (i < XN) {
        split_bf(X[i], h, l);
        g_xhi[i] = h; g_xlo[i] = l;
    } else {
        int w = i - XN;
        int which = w >> 20;
        int off = w & (WN - 1);
        float v = (which == 0 ? Wq : which == 1 ? Wk : Wv)[off];
        split_bf(v, h, l);
        g_whi[w] = h; g_wlo[w] = l;
    }
}

// ---------------------------------------------------------------------------
// K1: QKV via HMMA split-bf16.  CTA 128m x 64n, 8 warps (4m x 2n), warp tile
// 32x32 = 2 m-frags x 4 n-frags of m16n8k16. BK=32 double-buffered cp.async.
// 3-way split per k-step: AhBh + AhBl + AlBh -> fp32 acc. Pitch 40 bf16.
// FIXED (R14 bug): stage = 1536 16B units (4 chunks/row of 32 bf16), loader
// previously covered only half -> NaN from uninitialized smem.
// ---------------------------------------------------------------------------
#define QP 40                       // smem pitch in bf16
#define A_ELE (128 * QP)            // 5120 bf16 per A tile
#define B_ELE (64 * QP)             // 2560
#define STG_ELE (2 * A_ELE + 2 * B_ELE)   // 15360 bf16 = 30720 B
#define QKV_SMEM (2 * STG_ELE * 2)  // 61440 B

__global__ __launch_bounds__(256, 2) void qkv_kernel(
    const float* __restrict__ bq,
    const float* __restrict__ bk,
    const float* __restrict__ bv)
{
    extern __shared__ __nv_bfloat16 smh[];
    const unsigned smb = (unsigned)__cvta_generic_to_shared(smh);

    const int which = blockIdx.z;
    const int n0 = blockIdx.x * 64;
    const int m0 = blockIdx.y * 128;
    const int tid = threadIdx.x;
    const int wid = tid >> 5, lane = tid & 31;
    const int wm = wid & 3, wn = wid >> 2;        // warp grid 4m x 2n
    const int lq = lane >> 2, lr = lane & 3;      // lane quad structure

    const __nv_bfloat16* Wh = g_whi + (size_t)which * WN;
    const __nv_bfloat16* Wl = g_wlo + (size_t)which * WN;
    const float* bias = which == 0 ? bq : which == 1 ? bk : bv;
    float* dst = which == 0 ? g_q : which == 1 ? g_k : g_v;

    // stage loader: 1536 cpa16 units -> 6 per thread
    // A tiles: 128 rows x 4 chunks (32 bf16 = 64B). B tiles: 64 rows x 4.
    auto load_stage = [&](int st, int k0) {
        unsigned base = smb + (unsigned)(st * STG_ELE) * 2u;
        #pragma unroll
        for (int it = 0; it < 6; it++) {
            int u = tid + it * 256;
            unsigned dstp;
            const __nv_bfloat16* src;
            if (u < 512) {            // A hi
                int r = u >> 2, g = u & 3;
                dstp = base + (unsigned)(r * QP + g * 8) * 2u;
                src = g_xhi + (size_t)(m0 + r) * HIDDEN + k0 + g * 8;
            } else if (u < 1024) {    // A lo
                int v = u - 512; int r = v >> 2, g = v & 3;
                dstp = base + (unsigned)(A_ELE + r * QP + g * 8) * 2u;
                src = g_xlo + (size_t)(m0 + r) * HIDDEN + k0 + g * 8;
            } else if (u < 1280) {    // B hi
                int v = u - 1024; int r = v >> 2, g = v & 3;
                dstp = base + (unsigned)(2 * A_ELE + r * QP + g * 8) * 2u;
                src = Wh + (size_t)(n0 + r) * HIDDEN + k0 + g * 8;
            } else {                  // B lo
                int v = u - 1280; int r = v >> 2, g = v & 3;
                dstp = base + (unsigned)(2 * A_ELE + B_ELE + r * QP + g * 8) * 2u;
                src = Wl + (size_t)(n0 + r) * HIDDEN + k0 + g * 8;
            }
            cpa16(dstp, src);
        }
    };

    float acc[2][4][4];
    #pragma unroll
    for (int i = 0; i < 2; i++)
        #pragma unroll
        for (int j = 0; j < 4; j++)
            #pragma unroll
            for (int e = 0; e < 4; e++) acc[i][j][e] = 0.0f;

    load_stage(0, 0);
    CPA_COMMIT();

    for (int i = 0; i < 32; i++) {
        if (i < 31) { load_stage((i + 1) & 1, (i + 1) * 32); CPA_COMMIT(); CPA_WAIT1(); }
        else        { CPA_WAIT0(); }
        __syncthreads();

        const __nv_bfloat16* Ah = smh + (i & 1) * STG_ELE;
        const __nv_bfloat16* Al = Ah + A_ELE;
        const __nv_bfloat16* Bh = Ah + 2 * A_ELE;
        const __nv_bfloat16* Bl = Bh + B_ELE;

        #pragma unroll
        for (int ks = 0; ks < 32; ks += 16) {
            // A frags (2 m-subtiles, hi+lo): canonical m16n8k16 lane map
            unsigned ah[2][4], al[2][4];
            #pragma unroll
            for (int ms = 0; ms < 2; ms++) {
                int r1 = wm * 32 + ms * 16 + lq;
                int r2 = r1 + 8;
                int kc = ks + lr * 2;
                ah[ms][0] = *(const unsigned*)&Ah[r1 * QP + kc];
                ah[ms][1] = *(const unsigned*)&Ah[r2 * QP + kc];
                ah[ms][2] = *(const unsigned*)&Ah[r1 * QP + kc + 8];
                ah[ms][3] = *(const unsigned*)&Ah[r2 * QP + kc + 8];
                al[ms][0] = *(const unsigned*)&Al[r1 * QP + kc];
                al[ms][1] = *(const unsigned*)&Al[r2 * QP + kc];
                al[ms][2] = *(const unsigned*)&Al[r1 * QP + kc + 8];
                al[ms][3] = *(const unsigned*)&Al[r2 * QP + kc + 8];
            }
            // B frags (4 n-subtiles, hi+lo)
            unsigned bh[4][2], bl[4][2];
            #pragma unroll
            for (int ns = 0; ns < 4; ns++) {
                int n = wn * 32 + ns * 8 + lq;
                int kc = ks + lr * 2;
                bh[ns][0] = *(const unsigned*)&Bh[n * QP + kc];
                bh[ns][1] = *(const unsigned*)&Bh[n * QP + kc + 8];
                bl[ns][0] = *(const unsigned*)&Bl[n * QP + kc];
                bl[ns][1] = *(const unsigned*)&Bl[n * QP + kc + 8];
            }
            #pragma unroll
            for (int ms = 0; ms < 2; ms++)
                #pragma unroll
                for (int ns = 0; ns < 4; ns++) {
                    float* c = acc[ms][ns];
                    mma_bf16(c[0], c[1], c[2], c[3],
                             ah[ms][0], ah[ms][1], ah[ms][2], ah[ms][3],
                             bh[ns][0], bh[ns][1]);
                    mma_bf16(c[0], c[1], c[2], c[3],
                             ah[ms][0], ah[ms][1], ah[ms][2], ah[ms][3],
                             bl[ns][0], bl[ns][1]);
                    mma_bf16(c[0], c[1], c[2], c[3],
                             al[ms][0], al[ms][1], al[ms][2], al[ms][3],
                             bh[ns][0], bh[ns][1]);
                }
        }
        __syncthreads();
    }

    // epilogue: bias + store fp32 to [bh][s][d] (n-tile = exactly one head)
    const int head = n0 >> 6;
    #pragma unroll
    for (int ms = 0; ms < 2; ms++) {
        #pragma unroll
        for (int ns = 0; ns < 4; ns++) {
            int d = (wn * 32 + ns * 8 + lr * 2) & 63;
            float b0 = bias[n0 + wn * 32 + ns * 8 + lr * 2];
            float b1 = bias[n0 + wn * 32 + ns * 8 + lr * 2 + 1];
            #pragma unroll
            for (int half = 0; half < 2; half++) {
                int m = m0 + wm * 32 + ms * 16 + lq + half * 8;
                int batch = m >> 11, s = m & 2047;
                int bh_ = batch * NHEAD + head;
                float2 v = half == 0
                    ? make_float2(acc[ms][ns][0] + b0, acc[ms][ns][1] + b1)
                    : make_float2(acc[ms][ns][2] + b0, acc[ms][ns][3] + b1);
                *(float2*)&dst[((size_t)bh_ * SEQ + s) * HD + d] = v;
            }
        }
    }
}

// ---------------------------------------------------------------------------
// K2: scores (PROVEN round-9 SIMT). E = exp(QK^T/8) -> probs region + rsum.
// ---------------------------------------------------------------------------
#define SC_SMEM ((128 * 68 + 64 * 68) * 4)   // 52224 B

__global__ __launch_bounds__(256, 3) void scores_kernel(float* __restrict__ out)
{
    extern __shared__ float smf[];
    float* Qs = smf;              // [128 rows][68]
    float* Kt = smf + 128 * 68;   // [64 d][68 keys]

    const int kb = blockIdx.x;
    const int qb = blockIdx.y;
    const int bh = blockIdx.z;
    const int tid = threadIdx.x;
    const int ty = tid >> 4;
    const int tx = tid & 15;

    const float* Qp = g_q + ((size_t)bh * SEQ + qb * 128) * HD;
    const float* Kp = g_k + ((size_t)bh * SEQ + kb * 64) * HD;

    #pragma unroll
    for (int it = 0; it < 8; it++) {
        int f = tid + it * 256;
        int row = f >> 4;
        int c = (f & 15) << 2;
        *(float4*)&Qs[row * 68 + c] = *(const float4*)&Qp[(size_t)row * HD + c];
    }
    #pragma unroll
    for (int it = 0; it < 4; it++) {
        int f = tid + it * 256;
        int key = f >> 4;
        int c = (f & 15) << 2;
        float4 v = *(const float4*)&Kp[(size_t)key * HD + c];
        Kt[(c + 0) * 68 + key] = v.x; Kt[(c + 1) * 68 + key] = v.y;
        Kt[(c + 2) * 68 + key] = v.z; Kt[(c + 3) * 68 + key] = v.w;
    }
    __syncthreads();

    u64 acc[8][2];
    #pragma unroll
    for (int i = 0; i < 8; i++) { acc[i][0] = 0ull; acc[i][1] = 0ull; }

    #pragma unroll 8
    for (int dd = 0; dd < HD; dd++) {
        u64 b0 = *(const u64*)&Kt[dd * 68 + 2 * tx];
        u64 b1 = *(const u64*)&Kt[dd * 68 + 32 + 2 * tx];
        #pragma unroll
        for (int r = 0; r < 8; r++) {
            u64 ap = pack2(Qs[(ty * 8 + r) * 68 + dd]);
            fma2(acc[r][0], ap, b0);
            fma2(acc[r][1], ap, b1);
        }
    }

    float* Ebase = out + CTX_SIZE + ((size_t)bh * SEQ + qb * 128) * SEQ + kb * 64;
    #pragma unroll
    for (int r = 0; r < 8; r++) {
        int row = ty * 8 + r;
        float s0, s1, s2, s3;
        unpack2(acc[r][0], s0, s1);
        unpack2(acc[r][1], s2, s3);
        float e0 = fexp(s0 * 0.125f), e1 = fexp(s1 * 0.125f);
        float e2 = fexp(s2 * 0.125f), e3 = fexp(s3 * 0.125f);
        *(float2*)&Ebase[(size_t)row * SEQ + 2 * tx]      = make_float2(e0, e1);
        *(float2*)&Ebase[(size_t)row * SEQ + 32 + 2 * tx] = make_float2(e2, e3);
        float rs = (e0 + e1) + (e2 + e3);
        #pragma unroll
        for (int o = 8; o > 0; o >>= 1)
            rs += __shfl_xor_sync(0xffffffffu, rs, o, 16);
        if (tx == 0)
            atomicAdd(&g_rsum[(size_t)bh * SEQ + qb * 128 + row], rs);
    }
}

// ---------------------------------------------------------------------------
// K3: ctx (PROVEN round-9 SIMT, cp.async double-buffered).
// ---------------------------------------------------------------------------
#define ESZ (128 * 68)
#define VSZ (64 * 68)
#define CT_SMEM ((2 * ESZ + 2 * VSZ) * 4)   // 104448 B

__global__ __launch_bounds__(256, 2) void ctx_kernel(float* __restrict__ out)
{
    extern __shared__ float smf[];
    __shared__ float rinv_s[128];
    const unsigned smb = (unsigned)__cvta_generic_to_shared(smf);

    const int qb = blockIdx.x;
    const int bh = blockIdx.y;
    const int batch = bh >> 4;
    const int h = bh & 15;
    const int tid = threadIdx.x;
    const int ty = tid >> 4;
    const int tx = tid & 15;

    if (tid < 128)
        rinv_s[tid] = 1.0f / g_rsum[(size_t)bh * SEQ + qb * 128 + tid];

    float* Erow = out + CTX_SIZE + ((size_t)bh * SEQ + qb * 128) * SEQ;
    const float* Vp = g_v + (size_t)bh * SEQ * HD;

    auto load_stage = [&](int s, int k0) {
        unsigned Es = smb + (unsigned)(s * ESZ) * 4u;
        unsigned Vs = smb + (unsigned)(2 * ESZ + s * VSZ) * 4u;
        #pragma unroll
        for (int it = 0; it < 8; it++) {
            int f = tid + it * 256;
            int row = f >> 4;
            int kc = (f & 15) << 2;
            cpa16(Es + (unsigned)(row * 68 + kc) * 4u,
                  &Erow[(size_t)row * SEQ + k0 + kc]);
        }
        #pragma unroll
        for (int it = 0; it < 4; it++) {
            int f = tid + it * 256;
            int key = f >> 4;
            int c = (f & 15) << 2;
            cpa16(Vs + (unsigned)(key * 68 + c) * 4u,
                  &Vp[(size_t)(k0 + key) * HD + c]);
        }
    };

    u64 acc[8][2];
    #pragma unroll
    for (int i = 0; i < 8; i++) { acc[i][0] = 0ull; acc[i][1] = 0ull; }

    load_stage(0, 0);
    CPA_COMMIT();

    for (int i = 0; i < 32; i++) {
        if (i < 31) { load_stage((i + 1) & 1, (i + 1) * 64); CPA_COMMIT(); CPA_WAIT1(); }
        else        { CPA_WAIT0(); }
        __syncthreads();

        const float* Es = smf + (i & 1) * ESZ;
        const float* Vs = smf + 2 * ESZ + (i & 1) * VSZ;
        const int k0 = i * 64;

        #pragma unroll
        for (int it = 0; it < 8; it++) {
            int f = tid + it * 256;
            int row = f >> 4;
            int kc = (f & 15) << 2;
            float ri = rinv_s[row];
            float4 v = *(const float4*)&Es[row * 68 + kc];
            v.x *= ri; v.y *= ri; v.z *= ri; v.w *= ri;
            *(float4*)&Erow[(size_t)row * SEQ + k0 + kc] = v;
        }

        #pragma unroll 8
        for (int kk = 0; kk < 64; kk++) {
            u64 b0 = *(const u64*)&Vs[kk * 68 + 2 * tx];
            u64 b1 = *(const u64*)&Vs[kk * 68 + 32 + 2 * tx];
            #pragma unroll
            for (int r = 0; r < 8; r++) {
                u64 ap = pack2(Es[(ty * 8 + r) * 68 + kk]);
                fma2(acc[r][0], ap, b0);
                fma2(acc[r][1], ap, b1);
            }
        }
        __syncthreads();
    }

    #pragma unroll
    for (int r = 0; r < 8; r++) {
        int row = ty * 8 + r;
        float ri = rinv_s[row];
        int s = qb * 128 + row;
        float* p = out + ((size_t)batch * SEQ + s) * HIDDEN + h * HD;
        float x0, x1, x2, x3;
        unpack2(acc[r][0], x0, x1);
        unpack2(acc[r][1], x2, x3);
        *(float2*)&p[2 * tx]      = make_float2(x0 * ri, x1 * ri);
        *(float2*)&p[32 + 2 * tx] = make_float2(x2 * ri, x3 * ri);
    }
}

// ---------------------------------------------------------------------------
extern "C" void kernel_launch(void* const* d_in, const int* in_sizes, int n_in,
                              void* d_out, int out_size)
{
    const float* X  = (const float*)d_in[0];
    const float* Wq = (const float*)d_in[1];
    const float* bq = (const float*)d_in[2];
    const float* Wk = (const float*)d_in[3];
    const float* bk = (const float*)d_in[4];
    const float* Wv = (const float*)d_in[5];
    const float* bv = (const float*)d_in[6];
    float* out = (float*)d_out;

    zero_rsum_kernel<<<BH * SEQ / 256, 256>>>();
    split_kernel<<<(XN + 3 * WN) / 256, 256>>>(X, Wq, Wk, Wv);

    cudaFuncSetAttribute(qkv_kernel,
                         cudaFuncAttributeMaxDynamicSharedMemorySize, QKV_SMEM);
    dim3 g1(HIDDEN / 64, M_TOTAL / 128, 3);
    qkv_kernel<<<g1, 256, QKV_SMEM>>>(bq, bk, bv);

    cudaFuncSetAttribute(scores_kernel,
                         cudaFuncAttributeMaxDynamicSharedMemorySize, SC_SMEM);
    dim3 g2(SEQ / 64, SEQ / 128, BH);
    scores_kernel<<<g2, 256, SC_SMEM>>>(out);

    cudaFuncSetAttribute(ctx_kernel,
                         cudaFuncAttributeMaxDynamicSharedMemorySize, CT_SMEM);
    dim3 g3(SEQ / 128, BH);
    ctx_kernel<<<g3, 256, CT_SMEM>>>(out);
}